// round 5
// baseline (speedup 1.0000x reference)
#include <cuda_runtime.h>
#include <cuda_bf16.h>
#include <math.h>
#include <stdint.h>

// ---------------- problem constants ----------------
#define Bsz 1024
#define Dd 64
#define Mm 3
#define Cc 16384

#define TILE_C 128               // c per CTA
#define NTILES (Cc / TILE_C)     // 128 c-tiles
#define TILE_B 128               // b per CTA
#define NBT (Bsz / TILE_B)       // 8 b-chunks
#define THREADS 256

// SW128 swizzle: xor 16B-chunk index with row%8 (rows are 128B)
#define SWZ(o) ((o) ^ (((o) >> 3) & 0x70))

// ---------------- device scratch ----------------
__device__ float g_partial[2u * Mm * NTILES * Bsz];      // 3 MB
__device__ float g_bpart[48];
__device__ int   g_sync;                                 // zero-init; reset by last block

// ---------------- PTX helpers (family-portable) ----------------
__device__ __forceinline__ uint32_t smem_u32(const void* p) {
    uint32_t a;
    asm("{ .reg .u64 t; cvta.to.shared.u64 t, %1; cvt.u32.u64 %0, t; }" : "=r"(a) : "l"(p));
    return a;
}
__device__ __forceinline__ void ldsm_x4(uint32_t* r, uint32_t addr) {
    asm volatile("ldmatrix.sync.aligned.m8n8.x4.shared.b16 {%0,%1,%2,%3}, [%4];"
                 : "=r"(r[0]), "=r"(r[1]), "=r"(r[2]), "=r"(r[3]) : "r"(addr));
}
__device__ __forceinline__ void ldsm_x2(uint32_t* r, uint32_t addr) {
    asm volatile("ldmatrix.sync.aligned.m8n8.x2.shared.b16 {%0,%1}, [%2];"
                 : "=r"(r[0]), "=r"(r[1]) : "r"(addr));
}
__device__ __forceinline__ void mma_bf16(float* d, const uint32_t* a, const uint32_t* b) {
    asm volatile("mma.sync.aligned.m16n8k16.row.col.f32.bf16.bf16.f32 "
                 "{%0,%1,%2,%3}, {%4,%5,%6,%7}, {%8,%9}, {%0,%1,%2,%3};"
                 : "+f"(d[0]), "+f"(d[1]), "+f"(d[2]), "+f"(d[3])
                 : "r"(a[0]), "r"(a[1]), "r"(a[2]), "r"(a[3]), "r"(b[0]), "r"(b[1]));
}
__device__ __forceinline__ uint32_t pack_bf16x2(float lo, float hi) {
    __nv_bfloat162 v = __floats2bfloat162_rn(lo, hi);
    return *(uint32_t*)&v;
}

// ---------------- kernel 1: mma.sync GEMM + fused cvt + exp/row-sum ----------------
// D[b, c]: A = features (rows=b, K=64 k-major), B = centroids (rows=c, k-major).
// Staging reads fp32 GMEM directly, converting to bf16 into SW128 smem (kills
// the separate cvt kernel). Warp grid: 4 b-bands x 2 c-halves; 64 mma/warp.
// Epilogue: exp(acc * log2e/conc[c]) per-row sums, quad-shfl reduce, all
// fixed-order -> deterministic.
__global__ __launch_bounds__(THREADS)
void pcl_mma_kernel(const float* __restrict__ f0, const float* __restrict__ f1,
                    const float* __restrict__ cen0, const float* __restrict__ cen1,
                    const float* __restrict__ conc0, const float* __restrict__ conc1)
{
    __shared__ float sc[TILE_C];                     // log2e / conc[c]
    __shared__ __align__(16) char smA[TILE_B * 128]; // features  bf16 SW128 (16 KB)
    __shared__ __align__(16) char smB[TILE_C * 128]; // centroids bf16 SW128 (16 KB)
    __shared__ float ppart[2][TILE_B];               // per c-half row sums

    const int tid = threadIdx.x, wid = tid >> 5, lane = tid & 31;
    const int wrow = wid & 3;          // b-band (32 rows)
    const int wcol = wid >> 2;         // c-half (64 cols)
    const int bchunk = blockIdx.x & (NBT - 1);
    const int ctile  = blockIdx.x >> 3;       // 8 consumers of a ctile are adjacent -> L2 hits
    const int m = blockIdx.y, branch = blockIdx.z;

    const float* cen_f = (branch ? cen1 : cen0)
                         + ((size_t)m * Cc + (size_t)ctile * TILE_C) * Dd;
    const float* fb_f  = (branch ? f0 : f1)          // branch 0 pairs with features_I
                         + (size_t)bchunk * TILE_B * Dd;
    const float* conc  = branch ? conc1 : conc0;

    if (tid < TILE_C)
        sc[tid] = 1.4426950408889634f / conc[m * Cc + ctile * TILE_C + tid];

    // stage + convert both tiles: each i covers 16B bf16 (= 8 k) of one row
    {
        const float4* fsrc = (const float4*)fb_f;
        const float4* csrc = (const float4*)cen_f;
        #pragma unroll
        for (int i = tid; i < 1024; i += THREADS) {
            int row = i >> 3, q = i & 7;
            int s = row * 16 + q * 2;            // two float4 per 8 k
            float4 alo = fsrc[s], ahi = fsrc[s + 1];
            float4 blo = csrc[s], bhi = csrc[s + 1];
            uint4 av, bv;
            av.x = pack_bf16x2(alo.x, alo.y);  av.y = pack_bf16x2(alo.z, alo.w);
            av.z = pack_bf16x2(ahi.x, ahi.y);  av.w = pack_bf16x2(ahi.z, ahi.w);
            bv.x = pack_bf16x2(blo.x, blo.y);  bv.y = pack_bf16x2(blo.z, blo.w);
            bv.z = pack_bf16x2(bhi.x, bhi.y);  bv.w = pack_bf16x2(bhi.z, bhi.w);
            *(uint4*)(smA + SWZ(row * 128 + q * 16)) = av;
            *(uint4*)(smB + SWZ(row * 128 + q * 16)) = bv;
        }
    }
    __syncthreads();

    const uint32_t smA32 = smem_u32(smA);
    const uint32_t smB32 = smem_u32(smB);

    const int a_row_in = ((lane >> 3) & 1) * 8 + (lane & 7); // 0..15 within m-tile
    const int a_kofs   = (lane >> 4) * 8;                    // 0 or 8
    const int bl       = lane & 15;
    const int b_row_in = bl & 7;
    const int b_kofs   = ((bl >> 3) & 1) * 8;

    float acc[2][8][4];
    #pragma unroll
    for (int mt = 0; mt < 2; ++mt)
        #pragma unroll
        for (int n = 0; n < 8; ++n)
            #pragma unroll
            for (int i = 0; i < 4; ++i) acc[mt][n][i] = 0.f;

    #pragma unroll
    for (int k4 = 0; k4 < 4; ++k4) {
        const int kb = k4 * 16;
        uint32_t afr[2][4];
        #pragma unroll
        for (int mt = 0; mt < 2; ++mt) {
            int row = wrow * 32 + mt * 16 + a_row_in;
            ldsm_x4(afr[mt], smA32 + SWZ(row * 128 + (kb + a_kofs) * 2));
        }
        #pragma unroll
        for (int n = 0; n < 8; ++n) {
            uint32_t bfr[2];
            int row = wcol * 64 + n * 8 + b_row_in;
            ldsm_x2(bfr, smB32 + SWZ(row * 128 + (kb + b_kofs) * 2));
            mma_bf16(acc[0][n], afr[0], bfr);
            mma_bf16(acc[1][n], afr[1], bfr);
        }
    }

    // ---- epilogue: exp + per-row sums, registers only ----
    float scr[8][2];
    #pragma unroll
    for (int n = 0; n < 8; ++n) {
        int c0 = wcol * 64 + n * 8 + (lane & 3) * 2;
        scr[n][0] = sc[c0];
        scr[n][1] = sc[c0 + 1];
    }

    float rs[2][2] = {{0.f, 0.f}, {0.f, 0.f}};  // [m-tile][row-half]
    #pragma unroll
    for (int mt = 0; mt < 2; ++mt)
        #pragma unroll
        for (int n = 0; n < 8; ++n)
            #pragma unroll
            for (int i = 0; i < 4; ++i) {
                float x = acc[mt][n][i] * scr[n][i & 1];
                float e;
                asm("ex2.approx.ftz.f32 %0, %1;" : "=f"(e) : "f"(x));
                rs[mt][i >> 1] += e;
            }

    #pragma unroll
    for (int mt = 0; mt < 2; ++mt)
        #pragma unroll
        for (int h = 0; h < 2; ++h) {
            rs[mt][h] += __shfl_xor_sync(0xFFFFFFFFu, rs[mt][h], 1);
            rs[mt][h] += __shfl_xor_sync(0xFFFFFFFFu, rs[mt][h], 2);
        }

    if ((lane & 3) == 0) {
        #pragma unroll
        for (int mt = 0; mt < 2; ++mt)
            #pragma unroll
            for (int h = 0; h < 2; ++h)
                ppart[wcol][wrow * 32 + mt * 16 + h * 8 + (lane >> 2)] = rs[mt][h];
    }
    __syncthreads();

    if (tid < TILE_B) {
        g_partial[(((size_t)branch * Mm + m) * NTILES + ctile) * Bsz + bchunk * TILE_B + tid] =
            ppart[0][tid] + ppart[1][tid];
    }
}

// ---------------- kernel 2: fused finalize (last-block pattern) ----------------
__global__ __launch_bounds__(128)
void pcl_final_kernel(const float* __restrict__ f0, const float* __restrict__ f1,
                      const float* __restrict__ cen0, const float* __restrict__ cen1,
                      const float* __restrict__ conc0, const float* __restrict__ conc1,
                      const int* __restrict__ lab0, const int* __restrict__ lab1,
                      const int* __restrict__ lbp, float* __restrict__ out)
{
    const int tid = threadIdx.x;
    const int idx = blockIdx.x * 128 + tid;     // 48 x 128 = 6144
    const int branch = idx / (Mm * Bsz);
    const int r = idx % (Mm * Bsz);
    const int m = r / Bsz;
    const int b = r % Bsz;

    const float* f    = branch ? f0   : f1;
    const float* cen  = branch ? cen1 : cen0;
    const float* conc = branch ? conc1 : conc0;
    const int*   lab  = branch ? lab1 : lab0;

    const int c = lab[m * Bsz + b];
    const float* cv = cen + ((size_t)m * Cc + c) * Dd;
    const float* fv = f + (size_t)b * Dd;
    float dot = 0.f;
    #pragma unroll
    for (int k = 0; k < Dd; ++k) dot = fmaf(cv[k], fv[k], dot);
    const float logit = dot / conc[m * Cc + c];

    float se = 0.f;
    #pragma unroll 8
    for (int t = 0; t < NTILES; ++t)
        se += g_partial[(((size_t)branch * Mm + m) * NTILES + t) * Bsz + b];

    float local = logit - logf(se);

    __shared__ float red[128];
    red[tid] = local;
    __syncthreads();
    for (int s = 64; s > 0; s >>= 1) {
        if (tid < s) red[tid] += red[tid + s];
        __syncthreads();
    }

    if (tid == 0) {
        g_bpart[blockIdx.x] = red[0];
        __threadfence();
        int old = atomicAdd(&g_sync, 1);
        if (old == 47) {                      // last block: fixed-order final sum
            float s = 0.f;
            #pragma unroll
            for (int i = 0; i < 48; ++i) s += g_bpart[i];
            out[0] = -((float)lbp[0] * s) / (2.0f * (float)Bsz * (float)Mm);
            g_sync = 0;                       // reset for next graph replay
        }
    }
}

// ---------------- launch: 2 kernels total ----------------
extern "C" void kernel_launch(void* const* d_in, const int* in_sizes, int n_in,
                              void* d_out, int out_size)
{
    const float* f0    = (const float*)d_in[0];
    const float* f1    = (const float*)d_in[1];
    const float* cen0  = (const float*)d_in[2];
    const float* cen1  = (const float*)d_in[3];
    const float* conc0 = (const float*)d_in[4];
    const float* conc1 = (const float*)d_in[5];
    const int*   lab0  = (const int*)d_in[6];
    const int*   lab1  = (const int*)d_in[7];
    const int*   lbp   = (const int*)d_in[8];
    float* out = (float*)d_out;

    dim3 grid(NBT * NTILES, Mm, 2);   // 1024 x 3 x 2 = 6144 CTAs
    pcl_mma_kernel<<<grid, THREADS>>>(f0, f1, cen0, cen1, conc0, conc1);
    pcl_final_kernel<<<48, 128>>>(f0, f1, cen0, cen1, conc0, conc1,
                                  lab0, lab1, lbp, out);
}

// round 7
// speedup vs baseline: 1.3059x; 1.3059x over previous
#include <cuda_runtime.h>
#include <cuda_bf16.h>
#include <math.h>
#include <stdint.h>

// ---------------- problem constants ----------------
#define Bsz 1024
#define Dd 64
#define Mm 3
#define Cc 16384

#define TILE_C 128               // c per CTA
#define NTILES (Cc / TILE_C)     // 128 c-tiles
#define TILE_B 128               // b per CTA
#define NBT (Bsz / TILE_B)       // 8 b-chunks
#define THREADS 256

#define FIN_BLOCKS 768           // finalize: 6144 items, 1 warp each, 8 warps/block

// SW128 swizzle: xor 16B-chunk index with row%8 (rows are 128B)
#define SWZ(o) ((o) ^ (((o) >> 3) & 0x70))

// ---------------- device scratch ----------------
__device__ __nv_bfloat16 g_cenbf[2u * Mm * Cc * Dd];     // 12.6 MB
__device__ __nv_bfloat16 g_featbf[2u * Bsz * Dd];        // 256 KB (branch-ordered)
__device__ float g_partial[2u * Mm * NTILES * Bsz];      // 3 MB
__device__ float g_bpart[FIN_BLOCKS];
__device__ int   g_sync;                                 // zero-init; reset by last block

// ---------------- PTX helpers (family-portable) ----------------
__device__ __forceinline__ uint32_t smem_u32(const void* p) {
    uint32_t a;
    asm("{ .reg .u64 t; cvta.to.shared.u64 t, %1; cvt.u32.u64 %0, t; }" : "=r"(a) : "l"(p));
    return a;
}
__device__ __forceinline__ void ldsm_x4(uint32_t* r, uint32_t addr) {
    asm volatile("ldmatrix.sync.aligned.m8n8.x4.shared.b16 {%0,%1,%2,%3}, [%4];"
                 : "=r"(r[0]), "=r"(r[1]), "=r"(r[2]), "=r"(r[3]) : "r"(addr));
}
__device__ __forceinline__ void ldsm_x2(uint32_t* r, uint32_t addr) {
    asm volatile("ldmatrix.sync.aligned.m8n8.x2.shared.b16 {%0,%1}, [%2];"
                 : "=r"(r[0]), "=r"(r[1]) : "r"(addr));
}
__device__ __forceinline__ void mma_bf16(float* d, const uint32_t* a, const uint32_t* b) {
    asm volatile("mma.sync.aligned.m16n8k16.row.col.f32.bf16.bf16.f32 "
                 "{%0,%1,%2,%3}, {%4,%5,%6,%7}, {%8,%9}, {%0,%1,%2,%3};"
                 : "+f"(d[0]), "+f"(d[1]), "+f"(d[2]), "+f"(d[3])
                 : "r"(a[0]), "r"(a[1]), "r"(a[2]), "r"(a[3]), "r"(b[0]), "r"(b[1]));
}

// ---------------- kernel 1: fp32 -> bf16 conversion (round-4 proven) ----------------
__global__ __launch_bounds__(256)
void cvt_kernel(const float* __restrict__ f0, const float* __restrict__ f1,
                const float* __restrict__ cen0, const float* __restrict__ cen1)
{
    const int CEN4 = (Mm * Cc * Dd) / 4;
    const int FT4  = (Bsz * Dd) / 4;
    for (int i = blockIdx.x * blockDim.x + threadIdx.x; i < CEN4; i += gridDim.x * blockDim.x) {
        float4 a = ((const float4*)cen0)[i];
        float4 b = ((const float4*)cen1)[i];
        *(__nv_bfloat162*)&g_cenbf[(size_t)i * 4]     = __floats2bfloat162_rn(a.x, a.y);
        *(__nv_bfloat162*)&g_cenbf[(size_t)i * 4 + 2] = __floats2bfloat162_rn(a.z, a.w);
        *(__nv_bfloat162*)&g_cenbf[(size_t)(Mm*Cc*Dd) + (size_t)i * 4]     = __floats2bfloat162_rn(b.x, b.y);
        *(__nv_bfloat162*)&g_cenbf[(size_t)(Mm*Cc*Dd) + (size_t)i * 4 + 2] = __floats2bfloat162_rn(b.z, b.w);
        if (i < FT4) {
            float4 x = ((const float4*)f1)[i];   // branch 0 uses features_I
            float4 y = ((const float4*)f0)[i];   // branch 1 uses features
            *(__nv_bfloat162*)&g_featbf[(size_t)i * 4]     = __floats2bfloat162_rn(x.x, x.y);
            *(__nv_bfloat162*)&g_featbf[(size_t)i * 4 + 2] = __floats2bfloat162_rn(x.z, x.w);
            *(__nv_bfloat162*)&g_featbf[(size_t)(Bsz*Dd) + (size_t)i * 4]     = __floats2bfloat162_rn(y.x, y.y);
            *(__nv_bfloat162*)&g_featbf[(size_t)(Bsz*Dd) + (size_t)i * 4 + 2] = __floats2bfloat162_rn(y.z, y.w);
        }
    }
}

// ---------------- kernel 2: mma.sync GEMM + fused exp/row-sum (round-4 proven) ----------------
__global__ __launch_bounds__(THREADS)
void pcl_mma_kernel(const float* __restrict__ conc0, const float* __restrict__ conc1)
{
    __shared__ float sc[TILE_C];                     // log2e / conc[c]
    __shared__ __align__(16) char smA[TILE_B * 128]; // features  128 x 128B SW128
    __shared__ __align__(16) char smB[TILE_C * 128]; // centroids 128 x 128B SW128
    __shared__ float ppart[2][TILE_B];               // per c-half row sums

    const int tid = threadIdx.x, wid = tid >> 5, lane = tid & 31;
    const int wrow = wid & 3;          // b-band (32 rows)
    const int wcol = wid >> 2;         // c-half (64 cols)
    const int bchunk = blockIdx.x & (NBT - 1);
    const int ctile  = blockIdx.x >> 3;
    const int m = blockIdx.y, branch = blockIdx.z;

    const __nv_bfloat16* cenb = g_cenbf + (size_t)branch * (Mm * Cc * Dd)
                                + ((size_t)m * Cc + (size_t)ctile * TILE_C) * Dd;
    const __nv_bfloat16* fb   = g_featbf + (size_t)branch * (Bsz * Dd)
                                + (size_t)bchunk * TILE_B * Dd;
    const float* conc = branch ? conc1 : conc0;

    if (tid < TILE_C)
        sc[tid] = 1.4426950408889634f / conc[m * Cc + ctile * TILE_C + tid];

    {
        const uint4* fsrc = (const uint4*)fb;
        const uint4* csrc = (const uint4*)cenb;
        #pragma unroll
        for (int i = tid; i < 1024; i += THREADS) {
            int row = i >> 3, q = i & 7;
            *(uint4*)(smA + SWZ(row * 128 + q * 16)) = fsrc[i];
            *(uint4*)(smB + SWZ(row * 128 + q * 16)) = csrc[i];
        }
    }
    __syncthreads();

    const uint32_t smA32 = smem_u32(smA);
    const uint32_t smB32 = smem_u32(smB);

    const int a_row_in = ((lane >> 3) & 1) * 8 + (lane & 7);
    const int a_kofs   = (lane >> 4) * 8;
    const int bl       = lane & 15;
    const int b_row_in = bl & 7;
    const int b_kofs   = ((bl >> 3) & 1) * 8;

    float acc[2][8][4];
    #pragma unroll
    for (int mt = 0; mt < 2; ++mt)
        #pragma unroll
        for (int n = 0; n < 8; ++n)
            #pragma unroll
            for (int i = 0; i < 4; ++i) acc[mt][n][i] = 0.f;

    #pragma unroll
    for (int k4 = 0; k4 < 4; ++k4) {
        const int kb = k4 * 16;
        uint32_t afr[2][4];
        #pragma unroll
        for (int mt = 0; mt < 2; ++mt) {
            int row = wrow * 32 + mt * 16 + a_row_in;
            ldsm_x4(afr[mt], smA32 + SWZ(row * 128 + (kb + a_kofs) * 2));
        }
        #pragma unroll
        for (int n = 0; n < 8; ++n) {
            uint32_t bfr[2];
            int row = wcol * 64 + n * 8 + b_row_in;
            ldsm_x2(bfr, smB32 + SWZ(row * 128 + (kb + b_kofs) * 2));
            mma_bf16(acc[0][n], afr[0], bfr);
            mma_bf16(acc[1][n], afr[1], bfr);
        }
    }

    float scr[8][2];
    #pragma unroll
    for (int n = 0; n < 8; ++n) {
        int c0 = wcol * 64 + n * 8 + (lane & 3) * 2;
        scr[n][0] = sc[c0];
        scr[n][1] = sc[c0 + 1];
    }

    float rs[2][2] = {{0.f, 0.f}, {0.f, 0.f}};
    #pragma unroll
    for (int mt = 0; mt < 2; ++mt)
        #pragma unroll
        for (int n = 0; n < 8; ++n)
            #pragma unroll
            for (int i = 0; i < 4; ++i) {
                float x = acc[mt][n][i] * scr[n][i & 1];
                float e;
                asm("ex2.approx.ftz.f32 %0, %1;" : "=f"(e) : "f"(x));
                rs[mt][i >> 1] += e;
            }

    #pragma unroll
    for (int mt = 0; mt < 2; ++mt)
        #pragma unroll
        for (int h = 0; h < 2; ++h) {
            rs[mt][h] += __shfl_xor_sync(0xFFFFFFFFu, rs[mt][h], 1);
            rs[mt][h] += __shfl_xor_sync(0xFFFFFFFFu, rs[mt][h], 2);
        }

    if ((lane & 3) == 0) {
        #pragma unroll
        for (int mt = 0; mt < 2; ++mt)
            #pragma unroll
            for (int h = 0; h < 2; ++h)
                ppart[wcol][wrow * 32 + mt * 16 + h * 8 + (lane >> 2)] = rs[mt][h];
    }
    __syncthreads();

    if (tid < TILE_B) {
        g_partial[(((size_t)branch * Mm + m) * NTILES + ctile) * Bsz + bchunk * TILE_B + tid] =
            ppart[0][tid] + ppart[1][tid];
    }
}

// ---------------- kernel 3: finalize, warp-per-item (full-chip parallel) ----------------
__global__ __launch_bounds__(256)
void pcl_final_kernel(const float* __restrict__ f0, const float* __restrict__ f1,
                      const float* __restrict__ cen0, const float* __restrict__ cen1,
                      const float* __restrict__ conc0, const float* __restrict__ conc1,
                      const int* __restrict__ lab0, const int* __restrict__ lab1,
                      const int* __restrict__ lbp, float* __restrict__ out)
{
    const int tid = threadIdx.x, lane = tid & 31, w = tid >> 5;
    const int item = blockIdx.x * 8 + w;        // 0..6143
    const int branch = item / (Mm * Bsz);
    const int r = item % (Mm * Bsz);
    const int m = r / Bsz;
    const int b = r % Bsz;

    const float* f    = branch ? f0   : f1;
    const float* cen  = branch ? cen1 : cen0;
    const float* conc = branch ? conc1 : conc0;
    const int*   lab  = branch ? lab1 : lab0;

    const int c = lab[m * Bsz + b];

    // positive dot: 2 elems per lane
    const float2 cv = ((const float2*)(cen + ((size_t)m * Cc + c) * Dd))[lane];
    const float2 fv = ((const float2*)(f + (size_t)b * Dd))[lane];
    float dot = cv.x * fv.x + cv.y * fv.y;

    // sum-of-exp partials: 4 tiles per lane (high MLP across 196K warps)
    const float* gp = &g_partial[(((size_t)branch * Mm + m) * NTILES) * Bsz + b];
    float se = gp[(size_t)(lane)       * Bsz] + gp[(size_t)(lane + 32) * Bsz]
             + gp[(size_t)(lane + 64)  * Bsz] + gp[(size_t)(lane + 96) * Bsz];

    #pragma unroll
    for (int off = 16; off > 0; off >>= 1) {
        dot += __shfl_xor_sync(0xFFFFFFFFu, dot, off);
        se  += __shfl_xor_sync(0xFFFFFFFFu, se, off);
    }

    __shared__ float wsum[8];
    if (lane == 0)
        wsum[w] = dot / conc[m * Cc + c] - logf(se);
    __syncthreads();

    __shared__ int isLast;
    if (tid == 0) {
        float s = 0.f;
        #pragma unroll
        for (int i = 0; i < 8; ++i) s += wsum[i];
        g_bpart[blockIdx.x] = s;
        __threadfence();                               // release our partial
        isLast = (atomicAdd(&g_sync, 1) == FIN_BLOCKS - 1);
    }
    __syncthreads();

    if (isLast) {
        __threadfence();                               // acquire: others' partials
        float s = g_bpart[tid] + g_bpart[tid + 256] + g_bpart[tid + 512];
        __shared__ float red[256];
        red[tid] = s;
        __syncthreads();
        for (int st = 128; st > 0; st >>= 1) {
            if (tid < st) red[tid] += red[tid + st];
            __syncthreads();
        }
        if (tid == 0) {
            out[0] = -((float)lbp[0] * red[0]) / (2.0f * (float)Bsz * (float)Mm);
            g_sync = 0;   // reset for next graph replay
        }
    }
}

// ---------------- launch ----------------
extern "C" void kernel_launch(void* const* d_in, const int* in_sizes, int n_in,
                              void* d_out, int out_size)
{
    const float* f0    = (const float*)d_in[0];
    const float* f1    = (const float*)d_in[1];
    const float* cen0  = (const float*)d_in[2];
    const float* cen1  = (const float*)d_in[3];
    const float* conc0 = (const float*)d_in[4];
    const float* conc1 = (const float*)d_in[5];
    const int*   lab0  = (const int*)d_in[6];
    const int*   lab1  = (const int*)d_in[7];
    const int*   lbp   = (const int*)d_in[8];
    float* out = (float*)d_out;

    cvt_kernel<<<592, 256>>>(f0, f1, cen0, cen1);     // 4 full waves of 148

    dim3 grid(NBT * NTILES, Mm, 2);   // 1024 x 3 x 2 = 6144 CTAs
    pcl_mma_kernel<<<grid, THREADS>>>(conc0, conc1);

    pcl_final_kernel<<<FIN_BLOCKS, 256>>>(f0, f1, cen0, cen1, conc0, conc1,
                                          lab0, lab1, lbp, out);
}